// round 4
// baseline (speedup 1.0000x reference)
#include <cuda_runtime.h>

#define S_LEN 8192
#define DD 64
#define NBH 32            // B*H = 4*8
#define NSPLIT 16
#define CHUNK (S_LEN / NSPLIT)   // 512
#define TS 32             // rows per staged tile in k1
#define PART_KV 4096
#define PART_STRIDE 4160  // 64*64 KV + 64 ksum

__device__ float g_part[NBH * NSPLIT * PART_STRIDE];
__device__ float g_kv[NBH * PART_KV];
__device__ float g_ksum[NBH * DD];

typedef unsigned long long u64;

// phi(x) = elu(x)+1 = x>0 ? x+1 : exp(x)
__device__ __forceinline__ float phi(float x) {
    return x > 0.f ? x + 1.f : __expf(x);
}

// packed fp32x2 FMA: d = a*b + d (elementwise) — 2 FLOPs per issue slot
__device__ __forceinline__ void fma2(u64& d, u64 a, u64 b) {
    asm("fma.rn.f32x2 %0, %1, %2, %0;" : "+l"(d) : "l"(a), "l"(b));
}
__device__ __forceinline__ u64 dup2(float x) {
    u64 r;
    asm("mov.b64 %0, {%1, %1};" : "=l"(r) : "f"(x));
    return r;
}
__device__ __forceinline__ float2 unpack2(u64 v) {
    float2 r;
    asm("mov.b64 {%0, %1}, %2;" : "=f"(r.x), "=f"(r.y) : "l"(v));
    return r;
}

// ---------------------------------------------------------------------------
// Mask storage self-detection. The reference produces jnp.bool_ masks; the
// harness may transfer them as int32, float32, or raw bytes. Scan the first
// 128 words (512 bytes — in-bounds under every layout: byte layout needs
// 32768 B minimum) and classify. Misclassification prob with random 0/1
// masks ~ 2^-384.
//   mode 0: int32 (0/1 words)   mode 1: float32 (0f/1f words)   mode 2: bytes
// ---------------------------------------------------------------------------
__device__ __forceinline__ int mask_mode(const void* m) {
    const unsigned* w = (const unsigned*)m;
    bool i32 = true, f32 = true;
#pragma unroll 8
    for (int i = 0; i < 128; i++) {
        unsigned x = w[i];
        i32 &= (x <= 1u);
        f32 &= (x == 0u || x == 0x3F800000u);
    }
    return i32 ? 0 : (f32 ? 1 : 2);
}
__device__ __forceinline__ float mval(const void* m, long s, int mode) {
    if (mode == 0) return ((const int*)m)[s] ? 1.f : 0.f;
    if (mode == 1) return ((const float*)m)[s] != 0.f ? 1.f : 0.f;
    return ((const unsigned char*)m)[s] ? 1.f : 0.f;
}

// Transposed-q SMEM layout with XOR swizzle, conflict-free column writes:
// word index for logical (d, r):  d*64 + (r ^ (((d>>2)&15)<<1))
// mask is even -> preserves (even r, even r+1) pair contiguity + 8B alignment,
// so the GEMM reads (q[r],q[r+1]) as one LDS.64.
#define QT_IDX(d, r) (((d) << 6) + ((r) ^ ((((d) >> 2) & 15) << 1)))

// ---------------------------------------------------------------------------
// Kernel 1: partial KV[64][64] and ksum[64] per (bh, split).
// 256 threads as 16x16 grid; thread tile 4 rows (d of ke) x 4 cols (c of ve),
// packed as 2 row-pairs x 4 cols of f32x2.
// ---------------------------------------------------------------------------
__global__ void __launch_bounds__(256) k1_partial(
    const float* __restrict__ K, const float* __restrict__ V,
    const void* __restrict__ kvm)
{
    const int bh = blockIdx.x;
    const int split = blockIdx.y;
    const int b = bh >> 3;            // H = 8
    const int tid = threadIdx.x;
    const int i = tid >> 4;           // row group 0..15
    const int j = tid & 15;           // col group 0..15

    __shared__ __align__(16) float kbuf[TS][DD];
    __shared__ __align__(16) float vbuf[TS][DD];
    __shared__ __align__(16) float ksum_sh[16][DD];

    const int mmode = mask_mode(kvm);

    u64 acc[2][4];
#pragma unroll
    for (int rp = 0; rp < 2; rp++)
#pragma unroll
        for (int c = 0; c < 4; c++) acc[rp][c] = 0ull;
    float4 ksp = make_float4(0.f, 0.f, 0.f, 0.f);

    const long base = (long)bh * S_LEN;
    const int s0 = split * CHUNK;
    const long mbase = (long)b * S_LEN;

    for (int t = 0; t < CHUNK; t += TS) {
#pragma unroll
        for (int it = 0; it < 2; it++) {
            int idx = tid + it * 256;        // 0..511
            int row = idx >> 4;              // 0..31
            int c4 = (idx & 15) << 2;        // 0..60
            int s = s0 + t + row;
            float m = mval(kvm, mbase + s, mmode);
            float4 kr = *(const float4*)(K + (base + s) * DD + c4);
            float4 vr = *(const float4*)(V + (base + s) * DD + c4);
            float4 ke = make_float4(phi(kr.x) * m, phi(kr.y) * m,
                                    phi(kr.z) * m, phi(kr.w) * m);
            float4 ve = make_float4(vr.x * m, vr.y * m, vr.z * m, vr.w * m);
            *(float4*)&kbuf[row][c4] = ke;
            *(float4*)&vbuf[row][c4] = ve;
            ksp.x += ke.x; ksp.y += ke.y; ksp.z += ke.z; ksp.w += ke.w;
        }
        __syncthreads();
#pragma unroll
        for (int s = 0; s < TS; s++) {
            const u64* kp = (const u64*)&kbuf[s][i << 2];
            u64 ka0 = kp[0], ka1 = kp[1];    // pairs (4i,4i+1), (4i+2,4i+3)
            float4 vv = *(const float4*)&vbuf[s][j << 2];
            u64 b0 = dup2(vv.x), b1 = dup2(vv.y);
            u64 b2 = dup2(vv.z), b3 = dup2(vv.w);
            fma2(acc[0][0], ka0, b0); fma2(acc[0][1], ka0, b1);
            fma2(acc[0][2], ka0, b2); fma2(acc[0][3], ka0, b3);
            fma2(acc[1][0], ka1, b0); fma2(acc[1][1], ka1, b1);
            fma2(acc[1][2], ka1, b2); fma2(acc[1][3], ka1, b3);
        }
        __syncthreads();
    }

    float* outp = g_part + ((long)bh * NSPLIT + split) * PART_STRIDE;
#pragma unroll
    for (int rp = 0; rp < 2; rp++) {
        float2 c0 = unpack2(acc[rp][0]);
        float2 c1 = unpack2(acc[rp][1]);
        float2 c2 = unpack2(acc[rp][2]);
        float2 c3 = unpack2(acc[rp][3]);
        int r0 = (i << 2) + (rp << 1);
        *(float4*)(outp + r0 * DD + (j << 2)) = make_float4(c0.x, c1.x, c2.x, c3.x);
        *(float4*)(outp + (r0 + 1) * DD + (j << 2)) = make_float4(c0.y, c1.y, c2.y, c3.y);
    }
    *(float4*)&ksum_sh[i][j << 2] = ksp;
    __syncthreads();
    if (tid < DD) {
        float s = 0.f;
#pragma unroll
        for (int g = 0; g < 16; g++) s += ksum_sh[g][tid];
        outp[PART_KV + tid] = s;
    }
}

// ---------------------------------------------------------------------------
// Kernel 2: reduce 16 split-partials -> KV, ksum per bh. Fixed order.
// ---------------------------------------------------------------------------
__global__ void k2_reduce()
{
    int bh = blockIdx.x;
    const float* p = g_part + (long)bh * NSPLIT * PART_STRIDE;
    for (int e = threadIdx.x; e < PART_STRIDE; e += blockDim.x) {
        float s = 0.f;
#pragma unroll
        for (int sp = 0; sp < NSPLIT; sp++) s += p[sp * PART_STRIDE + e];
        if (e < PART_KV) g_kv[bh * PART_KV + e] = s;
        else             g_ksum[bh * DD + (e - PART_KV)] = s;
    }
}

// ---------------------------------------------------------------------------
// Kernel 3: out[l] = (phi(q)[l] @ KV) / (phi(q)[l] . ksum + 1e-6)
// Block: 256 rows of one bh (4 tiles of 64). KV resident in SMEM.
// Warp w covers rows w*8..w*8+7; lane covers cols 2*lane, 2*lane+1.
// Accumulators packed along row-pairs (f32x2); q pairs read via QT_IDX LDS.64.
// ---------------------------------------------------------------------------
__global__ void __launch_bounds__(256) k3_out(
    const float* __restrict__ Q, const void* __restrict__ qm,
    float* __restrict__ O)
{
    const int bh = blockIdx.y;
    const int b = bh >> 3;
    const int chunk = blockIdx.x;     // 0..31, 256 rows each
    const int tid = threadIdx.x;
    const int warp = tid >> 5;
    const int lane = tid & 31;

    __shared__ __align__(16) float kvb[DD][DD];
    __shared__ __align__(16) float qbT[DD * DD];
    __shared__ __align__(16) float ksum_s[DD];
    __shared__ __align__(16) float dinv[DD];

    const int mmode = mask_mode(qm);

    {
        const float4* src = (const float4*)(g_kv + bh * PART_KV);
        float4* dst = (float4*)&kvb[0][0];
        for (int e = tid; e < 1024; e += 256) dst[e] = src[e];
        if (tid < DD) ksum_s[tid] = g_ksum[bh * DD + tid];
    }
    __syncthreads();

    const long base = (long)bh * S_LEN;
    const long mbase = (long)b * S_LEN;
    const int w8 = warp << 3;

    for (int tile = 0; tile < 4; tile++) {
        const int row0 = chunk * 256 + tile * 64;

        // Stage phi(q)*mask transposed (swizzled) + per-row denominator.
#pragma unroll
        for (int it = 0; it < 4; it++) {
            int idx = tid + it * 256;         // 0..1023
            int row = idx >> 4;               // 0..63
            int c4 = (idx & 15) << 2;         // 0..60
            int grow = row0 + row;
            float m = mval(qm, mbase + grow, mmode);
            float4 qr = *(const float4*)(Q + (base + grow) * DD + c4);
            float4 qe = make_float4(phi(qr.x) * m, phi(qr.y) * m,
                                    phi(qr.z) * m, phi(qr.w) * m);
            qbT[QT_IDX(c4 + 0, row)] = qe.x;
            qbT[QT_IDX(c4 + 1, row)] = qe.y;
            qbT[QT_IDX(c4 + 2, row)] = qe.z;
            qbT[QT_IDX(c4 + 3, row)] = qe.w;
            float4 ks = *(const float4*)&ksum_s[c4];
            float dp = qe.x * ks.x + qe.y * ks.y + qe.z * ks.z + qe.w * ks.w;
            dp += __shfl_xor_sync(0xffffffffu, dp, 1);
            dp += __shfl_xor_sync(0xffffffffu, dp, 2);
            dp += __shfl_xor_sync(0xffffffffu, dp, 4);
            dp += __shfl_xor_sync(0xffffffffu, dp, 8);
            if ((lane & 15) == 0) dinv[row] = 1.f / (dp + 1e-6f);
        }
        __syncthreads();

        u64 acc[4][2];
#pragma unroll
        for (int rp = 0; rp < 4; rp++) { acc[rp][0] = 0ull; acc[rp][1] = 0ull; }

#pragma unroll
        for (int d = 0; d < DD; d++) {
            float2 kv2 = *(const float2*)&kvb[d][lane << 1];
            u64 b0 = dup2(kv2.x), b1 = dup2(kv2.y);
#pragma unroll
            for (int rp = 0; rp < 4; rp++) {
                u64 a = *(const u64*)&qbT[QT_IDX(d, w8 + (rp << 1))];
                fma2(acc[rp][0], a, b0);
                fma2(acc[rp][1], a, b1);
            }
        }

#pragma unroll
        for (int rp = 0; rp < 4; rp++) {
            float2 p0 = unpack2(acc[rp][0]);   // (row r0, row r0+1) @ col c0
            float2 p1 = unpack2(acc[rp][1]);   // (row r0, row r0+1) @ col c1
            int r0 = w8 + (rp << 1);
            float dv0 = dinv[r0], dv1 = dinv[r0 + 1];
            long g0 = base + row0 + r0;
            *(float2*)(O + g0 * DD + (lane << 1)) =
                make_float2(p0.x * dv0, p1.x * dv0);
            *(float2*)(O + (g0 + 1) * DD + (lane << 1)) =
                make_float2(p0.y * dv1, p1.y * dv1);
        }
        __syncthreads();
    }
}

// ---------------------------------------------------------------------------
extern "C" void kernel_launch(void* const* d_in, const int* in_sizes, int n_in,
                              void* d_out, int out_size)
{
    const float* q = (const float*)d_in[0];
    const float* k = (const float*)d_in[1];
    const float* v = (const float*)d_in[2];
    const void* q_mask  = d_in[3];
    const void* kv_mask = d_in[4];
    float* out = (float*)d_out;

    k1_partial<<<dim3(NBH, NSPLIT), 256>>>(k, v, kv_mask);
    k2_reduce<<<NBH, 256>>>();
    k3_out<<<dim3(S_LEN / 256, NBH), 256>>>(q, q_mask, out);
}

// round 5
// speedup vs baseline: 1.0107x; 1.0107x over previous
#include <cuda_runtime.h>

#define S_LEN 8192
#define DD 64
#define NBH 32            // B*H = 4*8
#define NSPLIT 16
#define CHUNK (S_LEN / NSPLIT)   // 512
#define TS 32             // rows per staged tile in k1
#define PART_KV 4096
#define PART_STRIDE 4160  // 64*64 KV + 64 ksum

__device__ float g_part[NBH * NSPLIT * PART_STRIDE];
__device__ float g_kv[NBH * PART_KV];
__device__ float g_ksum[NBH * DD];

typedef unsigned long long u64;

// phi(x) = elu(x)+1 = x>0 ? x+1 : exp(x)
__device__ __forceinline__ float phi(float x) {
    return x > 0.f ? x + 1.f : __expf(x);
}

// packed fp32x2 FMA: d = a*b + d (elementwise) — 2 FLOPs per issue slot
__device__ __forceinline__ void fma2(u64& d, u64 a, u64 b) {
    asm("fma.rn.f32x2 %0, %1, %2, %0;" : "+l"(d) : "l"(a), "l"(b));
}
__device__ __forceinline__ u64 dup2(float x) {
    u64 r;
    asm("mov.b64 %0, {%1, %1};" : "=l"(r) : "f"(x));
    return r;
}
__device__ __forceinline__ float2 unpack2(u64 v) {
    float2 r;
    asm("mov.b64 {%0, %1}, %2;" : "=f"(r.x), "=f"(r.y) : "l"(v));
    return r;
}

// ---------------------------------------------------------------------------
// Mask storage self-detection. The reference produces jnp.bool_ masks; the
// harness may transfer them as int32, float32, or raw bytes. Scan the first
// 128 words (512 bytes — in-bounds under every layout: byte layout needs
// 32768 B minimum) and classify. Misclassification prob with random 0/1
// masks ~ 2^-384.
//   mode 0: int32 (0/1 words)   mode 1: float32 (0f/1f words)   mode 2: bytes
// ---------------------------------------------------------------------------
__device__ __forceinline__ int mask_mode(const void* m) {
    const unsigned* w = (const unsigned*)m;
    bool i32 = true, f32 = true;
#pragma unroll 8
    for (int i = 0; i < 128; i++) {
        unsigned x = w[i];
        i32 &= (x <= 1u);
        f32 &= (x == 0u || x == 0x3F800000u);
    }
    return i32 ? 0 : (f32 ? 1 : 2);
}
__device__ __forceinline__ float mval(const void* m, long s, int mode) {
    if (mode == 0) return ((const int*)m)[s] ? 1.f : 0.f;
    if (mode == 1) return ((const float*)m)[s] != 0.f ? 1.f : 0.f;
    return ((const unsigned char*)m)[s] ? 1.f : 0.f;
}

// Transposed-q SMEM layout with XOR swizzle, conflict-free column writes:
// word index for logical (d, r):  d*64 + (r ^ (((d>>2)&15)<<1))
// mask is even -> preserves (even r, even r+1) pair contiguity + 8B alignment,
// so the GEMM reads (q[r],q[r+1]) as one LDS.64.
#define QT_IDX(d, r) (((d) << 6) + ((r) ^ ((((d) >> 2) & 15) << 1)))

// ---------------------------------------------------------------------------
// Kernel 1: partial KV[64][64] and ksum[64] per (bh, split).
// 256 threads as 16x16 grid; thread tile 4 rows (d of ke) x 4 cols (c of ve),
// packed as 2 row-pairs x 4 cols of f32x2.
// ---------------------------------------------------------------------------
__global__ void __launch_bounds__(256) k1_partial(
    const float* __restrict__ K, const float* __restrict__ V,
    const void* __restrict__ kvm)
{
    const int bh = blockIdx.x;
    const int split = blockIdx.y;
    const int b = bh >> 3;            // H = 8
    const int tid = threadIdx.x;
    const int i = tid >> 4;           // row group 0..15
    const int j = tid & 15;           // col group 0..15

    __shared__ __align__(16) float kbuf[TS][DD];
    __shared__ __align__(16) float vbuf[TS][DD];
    __shared__ __align__(16) float ksum_sh[16][DD];

    const int mmode = mask_mode(kvm);

    u64 acc[2][4];
#pragma unroll
    for (int rp = 0; rp < 2; rp++)
#pragma unroll
        for (int c = 0; c < 4; c++) acc[rp][c] = 0ull;
    float4 ksp = make_float4(0.f, 0.f, 0.f, 0.f);

    const long base = (long)bh * S_LEN;
    const int s0 = split * CHUNK;
    const long mbase = (long)b * S_LEN;

    for (int t = 0; t < CHUNK; t += TS) {
#pragma unroll
        for (int it = 0; it < 2; it++) {
            int idx = tid + it * 256;        // 0..511
            int row = idx >> 4;              // 0..31
            int c4 = (idx & 15) << 2;        // 0..60
            int s = s0 + t + row;
            float m = mval(kvm, mbase + s, mmode);
            float4 kr = *(const float4*)(K + (base + s) * DD + c4);
            float4 vr = *(const float4*)(V + (base + s) * DD + c4);
            float4 ke = make_float4(phi(kr.x) * m, phi(kr.y) * m,
                                    phi(kr.z) * m, phi(kr.w) * m);
            float4 ve = make_float4(vr.x * m, vr.y * m, vr.z * m, vr.w * m);
            *(float4*)&kbuf[row][c4] = ke;
            *(float4*)&vbuf[row][c4] = ve;
            ksp.x += ke.x; ksp.y += ke.y; ksp.z += ke.z; ksp.w += ke.w;
        }
        __syncthreads();
#pragma unroll
        for (int s = 0; s < TS; s++) {
            const u64* kp = (const u64*)&kbuf[s][i << 2];
            u64 ka0 = kp[0], ka1 = kp[1];    // pairs (4i,4i+1), (4i+2,4i+3)
            float4 vv = *(const float4*)&vbuf[s][j << 2];
            u64 b0 = dup2(vv.x), b1 = dup2(vv.y);
            u64 b2 = dup2(vv.z), b3 = dup2(vv.w);
            fma2(acc[0][0], ka0, b0); fma2(acc[0][1], ka0, b1);
            fma2(acc[0][2], ka0, b2); fma2(acc[0][3], ka0, b3);
            fma2(acc[1][0], ka1, b0); fma2(acc[1][1], ka1, b1);
            fma2(acc[1][2], ka1, b2); fma2(acc[1][3], ka1, b3);
        }
        __syncthreads();
    }

    float* outp = g_part + ((long)bh * NSPLIT + split) * PART_STRIDE;
#pragma unroll
    for (int rp = 0; rp < 2; rp++) {
        float2 c0 = unpack2(acc[rp][0]);
        float2 c1 = unpack2(acc[rp][1]);
        float2 c2 = unpack2(acc[rp][2]);
        float2 c3 = unpack2(acc[rp][3]);
        int r0 = (i << 2) + (rp << 1);
        *(float4*)(outp + r0 * DD + (j << 2)) = make_float4(c0.x, c1.x, c2.x, c3.x);
        *(float4*)(outp + (r0 + 1) * DD + (j << 2)) = make_float4(c0.y, c1.y, c2.y, c3.y);
    }
    *(float4*)&ksum_sh[i][j << 2] = ksp;
    __syncthreads();
    if (tid < DD) {
        float s = 0.f;
#pragma unroll
        for (int g = 0; g < 16; g++) s += ksum_sh[g][tid];
        outp[PART_KV + tid] = s;
    }
}

// ---------------------------------------------------------------------------
// Kernel 2: reduce 16 split-partials -> KV, ksum per bh. Fixed order.
// ---------------------------------------------------------------------------
__global__ void k2_reduce()
{
    int bh = blockIdx.x;
    const float* p = g_part + (long)bh * NSPLIT * PART_STRIDE;
    for (int e = threadIdx.x; e < PART_STRIDE; e += blockDim.x) {
        float s = 0.f;
#pragma unroll
        for (int sp = 0; sp < NSPLIT; sp++) s += p[sp * PART_STRIDE + e];
        if (e < PART_KV) g_kv[bh * PART_KV + e] = s;
        else             g_ksum[bh * DD + (e - PART_KV)] = s;
    }
}

// ---------------------------------------------------------------------------
// Kernel 3: out[l] = (phi(q)[l] @ KV) / (phi(q)[l] . ksum + 1e-6)
// Block: 256 rows of one bh (4 tiles of 64). KV resident in SMEM.
// Warp w covers rows w*8..w*8+7; lane covers cols 2*lane, 2*lane+1.
// Accumulators packed along row-pairs (f32x2); q pairs read via QT_IDX LDS.64.
// ---------------------------------------------------------------------------
__global__ void __launch_bounds__(256) k3_out(
    const float* __restrict__ Q, const void* __restrict__ qm,
    float* __restrict__ O)
{
    const int bh = blockIdx.y;
    const int b = bh >> 3;
    const int chunk = blockIdx.x;     // 0..31, 256 rows each
    const int tid = threadIdx.x;
    const int warp = tid >> 5;
    const int lane = tid & 31;

    __shared__ __align__(16) float kvb[DD][DD];
    __shared__ __align__(16) float qbT[DD * DD];
    __shared__ __align__(16) float ksum_s[DD];
    __shared__ __align__(16) float dinv[DD];

    const int mmode = mask_mode(qm);

    {
        const float4* src = (const float4*)(g_kv + bh * PART_KV);
        float4* dst = (float4*)&kvb[0][0];
        for (int e = tid; e < 1024; e += 256) dst[e] = src[e];
        if (tid < DD) ksum_s[tid] = g_ksum[bh * DD + tid];
    }
    __syncthreads();

    const long base = (long)bh * S_LEN;
    const long mbase = (long)b * S_LEN;
    const int w8 = warp << 3;

    for (int tile = 0; tile < 4; tile++) {
        const int row0 = chunk * 256 + tile * 64;

        // Stage phi(q)*mask transposed (swizzled) + per-row denominator.
#pragma unroll
        for (int it = 0; it < 4; it++) {
            int idx = tid + it * 256;         // 0..1023
            int row = idx >> 4;               // 0..63
            int c4 = (idx & 15) << 2;         // 0..60
            int grow = row0 + row;
            float m = mval(qm, mbase + grow, mmode);
            float4 qr = *(const float4*)(Q + (base + grow) * DD + c4);
            float4 qe = make_float4(phi(qr.x) * m, phi(qr.y) * m,
                                    phi(qr.z) * m, phi(qr.w) * m);
            qbT[QT_IDX(c4 + 0, row)] = qe.x;
            qbT[QT_IDX(c4 + 1, row)] = qe.y;
            qbT[QT_IDX(c4 + 2, row)] = qe.z;
            qbT[QT_IDX(c4 + 3, row)] = qe.w;
            float4 ks = *(const float4*)&ksum_s[c4];
            float dp = qe.x * ks.x + qe.y * ks.y + qe.z * ks.z + qe.w * ks.w;
            dp += __shfl_xor_sync(0xffffffffu, dp, 1);
            dp += __shfl_xor_sync(0xffffffffu, dp, 2);
            dp += __shfl_xor_sync(0xffffffffu, dp, 4);
            dp += __shfl_xor_sync(0xffffffffu, dp, 8);
            if ((lane & 15) == 0) dinv[row] = 1.f / (dp + 1e-6f);
        }
        __syncthreads();

        u64 acc[4][2];
#pragma unroll
        for (int rp = 0; rp < 4; rp++) { acc[rp][0] = 0ull; acc[rp][1] = 0ull; }

#pragma unroll
        for (int d = 0; d < DD; d++) {
            float2 kv2 = *(const float2*)&kvb[d][lane << 1];
            u64 b0 = dup2(kv2.x), b1 = dup2(kv2.y);
#pragma unroll
            for (int rp = 0; rp < 4; rp++) {
                u64 a = *(const u64*)&qbT[QT_IDX(d, w8 + (rp << 1))];
                fma2(acc[rp][0], a, b0);
                fma2(acc[rp][1], a, b1);
            }
        }

#pragma unroll
        for (int rp = 0; rp < 4; rp++) {
            float2 p0 = unpack2(acc[rp][0]);   // (row r0, row r0+1) @ col c0
            float2 p1 = unpack2(acc[rp][1]);   // (row r0, row r0+1) @ col c1
            int r0 = w8 + (rp << 1);
            float dv0 = dinv[r0], dv1 = dinv[r0 + 1];
            long g0 = base + row0 + r0;
            *(float2*)(O + g0 * DD + (lane << 1)) =
                make_float2(p0.x * dv0, p1.x * dv0);
            *(float2*)(O + (g0 + 1) * DD + (lane << 1)) =
                make_float2(p0.y * dv1, p1.y * dv1);
        }
        __syncthreads();
    }
}

// ---------------------------------------------------------------------------
extern "C" void kernel_launch(void* const* d_in, const int* in_sizes, int n_in,
                              void* d_out, int out_size)
{
    const float* q = (const float*)d_in[0];
    const float* k = (const float*)d_in[1];
    const float* v = (const float*)d_in[2];
    const void* q_mask  = d_in[3];
    const void* kv_mask = d_in[4];
    float* out = (float*)d_out;

    k1_partial<<<dim3(NBH, NSPLIT), 256>>>(k, v, kv_mask);
    k2_reduce<<<NBH, 256>>>();
    k3_out<<<dim3(S_LEN / 256, NBH), 256>>>(q, q_mask, out);
}